// round 16
// baseline (speedup 1.0000x reference)
#include <cuda_runtime.h>
#include <cuda_bf16.h>
#include <math.h>

// Problem constants (fixed by reference setup_inputs)
#define BB 8
#define TT 16
#define CC 64
#define NN 4096          // H*W
#define KSEL 2048        // keep_k = N*(1-0.5)

#define CHUNKB 2         // batches per chunk (window incl. writes < L2)
#define BLKS_PER_BATCH 256
#define FULL 0xffffffffu

// Scratch (device globals — no allocation allowed; zero-initialized)
__device__ float g_sq[BB * TT * NN];             // sqrt(sum_c x^2) per (b,t,n), 2 MB
__device__ unsigned g_maskbits[BB * (NN / 32)];  // 1 bit per (b,n)
__device__ int g_cnt[BB];                        // per-batch counters (self-resetting)

// ---------------------------------------------------------------------------
// Histogram radix-256 top-K select, 256 threads, 16 scores per thread
// (n = 16j..16j+15). Exact threshold + lowest-index tie admit — same
// semantics as the verified R4-R15 select bodies.
// ---------------------------------------------------------------------------
__device__ void select_histo_256(int b) {
    __shared__ int s_hist[256];
    __shared__ int s_suf[256];
    __shared__ int s_wtot[8];
    __shared__ unsigned s_or[8], s_and[8];
    __shared__ unsigned s_mask[NN / 32];
    __shared__ int s_scan[8];

    const int j    = threadIdx.x;              // 0..255
    const int lane = j & 31;
    const int wid  = j >> 5;

    // --- scores: 16 per thread; per n, sum over t ascending then *1/T
    //     (same per-n arithmetic order as all verified rounds) ---
    unsigned u[16];
    {
        float acc[16];
#pragma unroll
        for (int i = 0; i < 16; ++i) acc[i] = 0.f;
        const float4* part = (const float4*)g_sq;
#pragma unroll
        for (int t = 0; t < TT; ++t) {
            size_t base = (size_t)(b * TT + t) * (NN / 4) + j * 4;
#pragma unroll
            for (int q = 0; q < 4; ++q) {
                float4 f = part[base + q];
                acc[q * 4 + 0] += f.x;
                acc[q * 4 + 1] += f.y;
                acc[q * 4 + 2] += f.z;
                acc[q * 4 + 3] += f.w;
            }
        }
        const float inv = 1.0f / (float)TT;
#pragma unroll
        for (int i = 0; i < 16; ++i) u[i] = __float_as_uint(acc[i] * inv);
    }
    if (j < NN / 32) s_mask[j] = 0u;

    // --- block OR / AND: common-prefix detection ---
    {
        unsigned ow = 0u, aw = 0xffffffffu;
#pragma unroll
        for (int i = 0; i < 16; ++i) { ow |= u[i]; aw &= u[i]; }
        ow = __reduce_or_sync(FULL, ow);
        aw = __reduce_and_sync(FULL, aw);
        if (lane == 0) { s_or[wid] = ow; s_and[wid] = aw; }
    }
    __syncthreads();
    unsigned orv  = s_or[0],  andv = s_and[0];
#pragma unroll
    for (int w = 1; w < 8; ++w) { orv |= s_or[w]; andv &= s_and[w]; }
    const unsigned diff = orv ^ andv;

    // --- histogram radix-256 rounds ---
    const int hb = diff ? (31 - __clz((int)diff)) : 0;
    int shift = (hb >= 7) ? (hb - 7) : 0;
    int det   = shift + 8;                      // lowest determined bit
    unsigned hi = (det < 32) ? (andv & ~((1u << det) - 1u)) : 0u;
    int G = 0;                                  // count(u > current prefix)

    for (;;) {
        s_hist[j] = 0;
        __syncthreads();

#pragma unroll
        for (int i = 0; i < 16; ++i) {
            if (det >= 32 || ((u[i] ^ hi) >> det) == 0u)
                atomicAdd(&s_hist[(u[i] >> shift) & 0xFF], 1);
        }
        __syncthreads();

        // suffix sums S_j = sum_{k>=j} hist[k]
        int v = s_hist[j];
#pragma unroll
        for (int d2 = 1; d2 < 32; d2 <<= 1) {
            int t = __shfl_down_sync(FULL, v, d2);
            if (lane + d2 < 32) v += t;
        }
        if (lane == 0) s_wtot[wid] = v;
        __syncthreads();
        int carry = 0;
#pragma unroll
        for (int w2 = 1; w2 < 8; ++w2)
            if (w2 > wid) carry += s_wtot[w2];
        int Sj = v + carry;
        s_suf[j] = Sj;
        int fj = (G + Sj >= KSEL) ? 1 : 0;
        int cnt = __syncthreads_count(fj);
        int d = cnt - 1;                        // largest feasible digit
        G += (d < 255) ? s_suf[d + 1] : 0;
        hi |= ((unsigned)d) << shift;
        det = shift;
        if (shift == 0) break;
        shift = (shift >= 8) ? (shift - 8) : 0;
        __syncthreads();
    }

    const unsigned thr = hi;
    const int need = KSEL - G;                  // ties, lowest index first

    // --- exclusive scan of equal-counts over 256 threads (index order) ---
    int e = 0;
#pragma unroll
    for (int i = 0; i < 16; ++i) e += (u[i] == thr);
    int v2 = e;
#pragma unroll
    for (int d = 1; d < 32; d <<= 1) {
        int t = __shfl_up_sync(FULL, v2, d);
        if (lane >= d) v2 += t;
    }
    if (lane == 31) s_scan[wid] = v2;
    __syncthreads();
    int wpre = 0;
#pragma unroll
    for (int w = 0; w < 8; ++w)
        if (w < wid) wpre += s_scan[w];
    int excl = v2 - e + wpre;

    // --- 16 mask bits for n = 16j..16j+15 ---
    unsigned bits16 = 0;
    int r = excl;
#pragma unroll
    for (int i = 0; i < 16; ++i) {
        if (u[i] > thr) {
            bits16 |= 1u << i;
        } else if (u[i] == thr) {
            if (r < need) bits16 |= 1u << i;
            ++r;
        }
    }
    atomicOr(&s_mask[j >> 1], bits16 << ((j & 1) * 16));
    __syncthreads();
    if (j < NN / 32) g_maskbits[b * (NN / 32) + j] = s_mask[j];
}

// ---------------------------------------------------------------------------
// K1S: chunk scoring (R1-proven 64-load form) + fused last-block select.
// 512 blocks x 256 threads per chunk; each block belongs to one batch.
// Last arrival per batch (atomic counter, NO spinning) runs the histogram
// select on its batch's L2-hot 256KB of sqrt-partials.
// ---------------------------------------------------------------------------
__global__ void __launch_bounds__(256) k1s(const float* __restrict__ x,
                                           int chunk) {
    const int idx = blockIdx.x * 256 + threadIdx.x;   // [0, 131072)
    const int n   = idx & (NN - 1);
    const int btl = idx >> 12;                        // 0..31 (const per block)
    const int bt  = chunk * (CHUNKB * TT) + btl;
    const int b   = chunk * CHUNKB + (btl >> 4);

    const float* p = x + (size_t)bt * CC * NN + n;
    float acc = 0.0f;
#pragma unroll
    for (int c = 0; c < CC; ++c) {
        float v = p[(size_t)c * NN];
        acc += v * v;
    }
    g_sq[(size_t)bt * NN + n] = sqrtf(acc);

    // release our partials, then count arrivals for this batch
    __threadfence();
    __shared__ int s_last;
    __syncthreads();
    if (threadIdx.x == 0) {
        int v = atomicAdd(&g_cnt[b], 1);
        s_last = (v == BLKS_PER_BATCH - 1);
        if (s_last) g_cnt[b] = 0;                 // self-reset for graph replay
    }
    __syncthreads();
    if (!s_last) return;

    __threadfence();                              // acquire all batch partials
    select_histo_256(b);
}

// ---------------------------------------------------------------------------
// M: masked copy for one 2-batch chunk (verified form). Reads hit x[chunk]'s
// L2 residue; evict-first on both streams.
// ---------------------------------------------------------------------------
__global__ void __launch_bounds__(256) k_mask(const float4* __restrict__ x4,
                                              float4* __restrict__ o4,
                                              int chunk) {
    unsigned i = (unsigned)chunk * (CHUNKB * TT * CC * (NN / 4))
               + blockIdx.x * 256 + threadIdx.x;
    int n4 = i & ((NN / 4) - 1);
    int b  = i >> 20;                        // 2^20 float4 per batch
    int n  = n4 << 2;
    unsigned mword = g_maskbits[(b << 7) + (n >> 5)];
    unsigned bits  = mword >> (n & 31);
    float4 v = __ldcs(&x4[(size_t)i]);
    v.x = (bits & 1u) ? v.x : 0.0f;
    v.y = (bits & 2u) ? v.y : 0.0f;
    v.z = (bits & 4u) ? v.z : 0.0f;
    v.w = (bits & 8u) ? v.w : 0.0f;
    __stcs(&o4[(size_t)i], v);
}

// ---------------------------------------------------------------------------
extern "C" void kernel_launch(void* const* d_in, const int* in_sizes, int n_in,
                              void* d_out, int out_size) {
    const float* x = (const float*)d_in[0];
    float* out = (float*)d_out;

    const int K_GRID = CHUNKB * TT * NN / 256;               // 512 blocks
    const int M_GRID = CHUNKB * TT * CC * NN / 4 / 256;      // 8192 blocks

    // 8 nodes. M(c) runs one chunk behind K1S so x(c) is L2-resident
    // (window: x(c) 33.5 + x(c+1) 33.5 + out(c) 33.5 + 2 MB partials < L2).
    k1s<<<K_GRID, 256>>>(x, 0);
    k1s<<<K_GRID, 256>>>(x, 1);
    k_mask<<<M_GRID, 256>>>((const float4*)x, (float4*)out, 0);
    k1s<<<K_GRID, 256>>>(x, 2);
    k_mask<<<M_GRID, 256>>>((const float4*)x, (float4*)out, 1);
    k1s<<<K_GRID, 256>>>(x, 3);
    k_mask<<<M_GRID, 256>>>((const float4*)x, (float4*)out, 2);
    k_mask<<<M_GRID, 256>>>((const float4*)x, (float4*)out, 3);
}

// round 17
// speedup vs baseline: 1.2108x; 1.2108x over previous
#include <cuda_runtime.h>
#include <cuda_bf16.h>
#include <math.h>

// Problem constants (fixed by reference setup_inputs)
#define BB 8
#define TT 16
#define CC 64
#define NN 4096          // H*W
#define KSEL 2048        // keep_k = N*(1-0.5)

#define CHUNKB 2         // batches per chunk
#define CGROUPS 4        // c-groups combined in-block
#define CPER 16          // channels per group
#define FULL 0xffffffffu

// Scratch (device globals — no allocation allowed)
__device__ float g_sq[BB * TT * NN];             // sqrt(sum_c x^2) per (b,t,n), 2 MB
__device__ unsigned g_maskbits[BB * (NN / 32)];  // 1 bit per (b,n)

// ---------------------------------------------------------------------------
// K1' (R12-verified, ~6.5us/chunk): chunk scoring with in-block c-group
// combine. 2048 blocks x 256 threads per chunk = 524288 threads, 16 loads
// each (full streaming MLP). Warp = 32 consecutive n at fixed cg (coalesced).
// ---------------------------------------------------------------------------
__global__ void __launch_bounds__(256) k1_score(const float* __restrict__ x,
                                                int chunk) {
    __shared__ float s_part[CGROUPS * 64];

    const int tid = threadIdx.x;
    const int cg  = tid >> 6;                  // 0..3
    const int nl  = tid & 63;                  // 0..63
    const int btl = blockIdx.x >> 6;           // 0..31
    const int nb  = blockIdx.x & 63;           // 0..63
    const int bt  = chunk * (CHUNKB * TT) + btl;
    const int n   = nb * 64 + nl;

    const float* p = x + (size_t)bt * CC * NN + (size_t)(cg * CPER) * NN + n;
    float acc = 0.0f;
#pragma unroll
    for (int c = 0; c < CPER; ++c) {
        float v = p[(size_t)c * NN];
        acc += v * v;
    }
    s_part[cg * 64 + nl] = acc;
    __syncthreads();

    if (tid < 64) {
        float total = s_part[tid] + s_part[64 + tid]
                    + s_part[128 + tid] + s_part[192 + tid];
        g_sq[(size_t)bt * NN + nb * 64 + tid] = sqrtf(total);
    }
}

// ---------------------------------------------------------------------------
// S (R14-verified, ~2.5us): per-batch exact top-K -> mask bits via histogram
// radix-256. Exact threshold + lowest-index tie admit.
// ---------------------------------------------------------------------------
__global__ void __launch_bounds__(1024, 1) k_select(int chunk) {
    __shared__ int s_hist[256];
    __shared__ int s_suf[256];
    __shared__ int s_wtot[8];
    __shared__ unsigned s_or[32], s_and[32];
    __shared__ unsigned s_mask[NN / 32];
    __shared__ int s_scan[32];

    const int b    = chunk * CHUNKB + blockIdx.x;
    const int j    = threadIdx.x;              // 0..1023
    const int lane = j & 31;
    const int wid  = j >> 5;

    // --- scores: 4 per thread, sequential over t (verified order) ---
    const float4* part = (const float4*)g_sq;
    float s0 = 0.f, s1 = 0.f, s2 = 0.f, s3 = 0.f;
#pragma unroll
    for (int t = 0; t < TT; ++t) {
        float4 f = part[(size_t)(b * TT + t) * (NN / 4) + j];
        s0 += f.x; s1 += f.y; s2 += f.z; s3 += f.w;
    }
    const float inv = 1.0f / (float)TT;
    unsigned u0 = __float_as_uint(s0 * inv);
    unsigned u1 = __float_as_uint(s1 * inv);
    unsigned u2 = __float_as_uint(s2 * inv);
    unsigned u3 = __float_as_uint(s3 * inv);

    if (j < NN / 32) s_mask[j] = 0u;

    // --- block OR / AND: common-prefix detection ---
    {
        unsigned ow = __reduce_or_sync(FULL, u0 | u1 | u2 | u3);
        unsigned aw = __reduce_and_sync(FULL, u0 & u1 & u2 & u3);
        if (lane == 0) { s_or[wid] = ow; s_and[wid] = aw; }
    }
    __syncthreads();
    const unsigned orv  = __reduce_or_sync(FULL, s_or[lane]);
    const unsigned andv = __reduce_and_sync(FULL, s_and[lane]);
    const unsigned diff = orv ^ andv;

    // --- histogram radix-256 select ---
    const int hb = diff ? (31 - __clz((int)diff)) : 0;
    int shift = (hb >= 7) ? (hb - 7) : 0;      // round 1 covers hb..hb-7
    int det   = shift + 8;                      // lowest determined bit
    unsigned hi = (det < 32) ? (andv & ~((1u << det) - 1u)) : 0u;
    int G = 0;                                  // count(u > current prefix)

    for (;;) {
        if (j < 256) s_hist[j] = 0;
        __syncthreads();

        if (det >= 32 || ((u0 ^ hi) >> det) == 0u)
            atomicAdd(&s_hist[(u0 >> shift) & 0xFF], 1);
        if (det >= 32 || ((u1 ^ hi) >> det) == 0u)
            atomicAdd(&s_hist[(u1 >> shift) & 0xFF], 1);
        if (det >= 32 || ((u2 ^ hi) >> det) == 0u)
            atomicAdd(&s_hist[(u2 >> shift) & 0xFF], 1);
        if (det >= 32 || ((u3 ^ hi) >> det) == 0u)
            atomicAdd(&s_hist[(u3 >> shift) & 0xFF], 1);
        __syncthreads();

        // suffix sums over 256 bins
        int h = (j < 256) ? s_hist[j] : 0;
        int v = h;
#pragma unroll
        for (int d2 = 1; d2 < 32; d2 <<= 1) {
            int t = __shfl_down_sync(FULL, v, d2);
            if (lane + d2 < 32) v += t;
        }
        if (j < 256 && lane == 0) s_wtot[wid] = v;
        __syncthreads();
        int fj = 0;
        if (j < 256) {
            int carry = 0;
#pragma unroll
            for (int w2 = 1; w2 < 8; ++w2)
                if (w2 > wid) carry += s_wtot[w2];
            int Sj = v + carry;
            s_suf[j] = Sj;
            fj = (G + Sj >= KSEL) ? 1 : 0;
        }
        int cnt = __syncthreads_count(fj);
        int d = cnt - 1;                        // largest feasible digit
        G += (d < 255) ? s_suf[d + 1] : 0;
        hi |= ((unsigned)d) << shift;
        det = shift;
        if (shift == 0) break;
        shift = (shift >= 8) ? (shift - 8) : 0;
        __syncthreads();
    }

    const unsigned thr = hi;
    const int need = KSEL - G;

    // --- exclusive scan of equal-counts (lowest-index tie admit) ---
    int e = (u0 == thr) + (u1 == thr) + (u2 == thr) + (u3 == thr);
    int v2 = e;
#pragma unroll
    for (int d = 1; d < 32; d <<= 1) {
        int t = __shfl_up_sync(FULL, v2, d);
        if (lane >= d) v2 += t;
    }
    if (lane == 31) s_scan[wid] = v2;
    __syncthreads();
    if (wid == 0) {
        int w = s_scan[lane];
#pragma unroll
        for (int d = 1; d < 32; d <<= 1) {
            int t = __shfl_up_sync(FULL, w, d);
            if (lane >= d) w += t;
        }
        s_scan[lane] = w;
    }
    __syncthreads();
    int excl = v2 - e + (wid ? s_scan[wid - 1] : 0);

    unsigned nib = 0;
    int r = excl;
    unsigned uu[4] = {u0, u1, u2, u3};
#pragma unroll
    for (int i = 0; i < 4; ++i) {
        if (uu[i] > thr) {
            nib |= 1u << i;
        } else if (uu[i] == thr) {
            if (r < need) nib |= 1u << i;
            ++r;
        }
    }
    atomicOr(&s_mask[j >> 3], nib << ((j & 7) * 4));
    __syncthreads();
    if (j < NN / 32) g_maskbits[b * (NN / 32) + j] = s_mask[j];
}

// ---------------------------------------------------------------------------
// M (verified, ~6us): masked copy for one 2-batch chunk; reads hit x[chunk]'s
// L2 residue (<=35 MB window since K1'(c)); evict-first on both streams.
// ---------------------------------------------------------------------------
__global__ void __launch_bounds__(256) k_mask(const float4* __restrict__ x4,
                                              float4* __restrict__ o4,
                                              int chunk) {
    unsigned i = (unsigned)chunk * (CHUNKB * TT * CC * (NN / 4))
               + blockIdx.x * 256 + threadIdx.x;
    int n4 = i & ((NN / 4) - 1);
    int b  = i >> 20;                        // 2^20 float4 per batch
    int n  = n4 << 2;
    unsigned mword = g_maskbits[(b << 7) + (n >> 5)];
    unsigned bits  = mword >> (n & 31);
    float4 v = __ldcs(&x4[(size_t)i]);
    v.x = (bits & 1u) ? v.x : 0.0f;
    v.y = (bits & 2u) ? v.y : 0.0f;
    v.z = (bits & 4u) ? v.z : 0.0f;
    v.w = (bits & 8u) ? v.w : 0.0f;
    __stcs(&o4[(size_t)i], v);
}

// ---------------------------------------------------------------------------
extern "C" void kernel_launch(void* const* d_in, const int* in_sizes, int n_in,
                              void* d_out, int out_size) {
    const float* x = (const float*)d_in[0];
    float* out = (float*)d_out;

    const int K1_GRID = CHUNKB * TT * 64;                   // 2048 blocks
    const int M_GRID  = CHUNKB * TT * CC * NN / 4 / 256;    // 8192 blocks

    // R13 schedule (verified residency windows), R14 select:
    // M(c) runs right after K1(c+1) -> <=35 MB between K1(c) and M(c).
    k1_score<<<K1_GRID, 256>>>(x, 0);
    k_select<<<CHUNKB, 1024>>>(0);
    k1_score<<<K1_GRID, 256>>>(x, 1);
    k_select<<<CHUNKB, 1024>>>(1);
    k_mask<<<M_GRID, 256>>>((const float4*)x, (float4*)out, 0);
    k1_score<<<K1_GRID, 256>>>(x, 2);
    k_select<<<CHUNKB, 1024>>>(2);
    k_mask<<<M_GRID, 256>>>((const float4*)x, (float4*)out, 1);
    k1_score<<<K1_GRID, 256>>>(x, 3);
    k_select<<<CHUNKB, 1024>>>(3);
    k_mask<<<M_GRID, 256>>>((const float4*)x, (float4*)out, 2);
    k_mask<<<M_GRID, 256>>>((const float4*)x, (float4*)out, 3);
}